// round 11
// baseline (speedup 1.0000x reference)
#include <cuda_runtime.h>
#include <cuda_bf16.h>
#include <math.h>

// ---------------------------------------------------------------------------
// Problem constants
// ---------------------------------------------------------------------------
#define T_TOKENS 8192   // B*S = 4*2048
#define D_MODEL  1024
#define D_FF     4096
#define N_HEADS  16
#define D_HEAD   64
#define SEQ      2048
#define BATCH    4

// ---------------------------------------------------------------------------
// Scratch (device globals; no allocation allowed)
// ---------------------------------------------------------------------------
__device__ float g_ln  [T_TOKENS * D_MODEL];
__device__ float g_q   [T_TOKENS * D_MODEL];
__device__ float g_k   [T_TOKENS * D_MODEL];
__device__ float g_v   [T_TOKENS * D_MODEL];
__device__ float g_attn[T_TOKENS * D_MODEL];
__device__ float g_x1  [T_TOKENS * D_MODEL];
__device__ float g_h   [T_TOKENS * D_FF];
// tf32-rounded AND transposed weights: Wt[n][k]
__device__ float g_wq[D_MODEL * D_MODEL];
__device__ float g_wk[D_MODEL * D_MODEL];
__device__ float g_wv[D_MODEL * D_MODEL];
__device__ float g_wo[D_MODEL * D_MODEL];
__device__ float g_w1[D_MODEL * D_FF];
__device__ float g_w2[D_FF * D_MODEL];

// ---------------------------------------------------------------------------
// Common helpers
// ---------------------------------------------------------------------------
__device__ __forceinline__ unsigned f2tf32(float x) {
    unsigned r;
    asm("cvt.rna.tf32.f32 %0, %1;" : "=r"(r) : "f"(x));
    return r;
}

__device__ __forceinline__ float round_tf32(float x) {
    return __uint_as_float(f2tf32(x));
}

__device__ __forceinline__ unsigned smem_u32(const void* p) {
    return (unsigned)__cvta_generic_to_shared(p);
}

__device__ __forceinline__ void ldsm_x4(unsigned& r0, unsigned& r1,
                                        unsigned& r2, unsigned& r3, unsigned addr) {
    asm volatile("ldmatrix.sync.aligned.m8n8.x4.shared.b16 {%0,%1,%2,%3}, [%4];"
                 : "=r"(r0), "=r"(r1), "=r"(r2), "=r"(r3) : "r"(addr));
}

__device__ __forceinline__ void mma_tf32(float& c0, float& c1, float& c2, float& c3,
                                         unsigned a0, unsigned a1, unsigned a2, unsigned a3,
                                         unsigned b0, unsigned b1) {
    asm volatile(
        "mma.sync.aligned.m16n8k8.row.col.f32.tf32.tf32.f32 "
        "{%0,%1,%2,%3}, {%4,%5,%6,%7}, {%8,%9}, {%0,%1,%2,%3};"
        : "+f"(c0), "+f"(c1), "+f"(c2), "+f"(c3)
        : "r"(a0), "r"(a1), "r"(a2), "r"(a3), "r"(b0), "r"(b1));
}

__device__ __forceinline__ void cp_async16(unsigned dst, const void* src) {
    asm volatile("cp.async.ca.shared.global [%0], [%1], 16;" :: "r"(dst), "l"(src));
}
#define CP_COMMIT()  asm volatile("cp.async.commit_group;")
#define CP_WAIT1()   asm volatile("cp.async.wait_group 1;")

__device__ __forceinline__ float gelu_tanh(float x) {
    float x3 = x * x * x;
    return 0.5f * x * (1.f + tanhf(0.7978845608028654f * (x + 0.044715f * x3)));
}

// ---------------------------------------------------------------------------
// Weight prep: tf32-round + transpose.  in: W[K,N]  out: Wt[N,K] (rounded)
// ---------------------------------------------------------------------------
__device__ __forceinline__ void rt_body(const float* __restrict__ in,
                                        float* __restrict__ out, int K, int N) {
    __shared__ float tile[32][33];
    int n0 = blockIdx.x * 32;
    int k0 = blockIdx.y * 32;
    #pragma unroll
    for (int i = threadIdx.y; i < 32; i += 8)
        tile[i][threadIdx.x] = in[(size_t)(k0 + i) * N + n0 + threadIdx.x];
    __syncthreads();
    #pragma unroll
    for (int i = threadIdx.y; i < 32; i += 8)
        out[(size_t)(n0 + i) * K + k0 + threadIdx.x] = round_tf32(tile[threadIdx.x][i]);
}

__global__ __launch_bounds__(256)
void round_transpose_kernel(const float* __restrict__ in, float* __restrict__ out,
                            int K, int N) {
    rt_body(in, out, K, N);
}

__global__ __launch_bounds__(256)
void round_transpose4_kernel(const float* __restrict__ i0, const float* __restrict__ i1,
                             const float* __restrict__ i2, const float* __restrict__ i3,
                             float* __restrict__ o0, float* __restrict__ o1,
                             float* __restrict__ o2, float* __restrict__ o3) {
    const float* in; float* out;
    if (blockIdx.z == 0)      { in = i0; out = o0; }
    else if (blockIdx.z == 1) { in = i1; out = o1; }
    else if (blockIdx.z == 2) { in = i2; out = o2; }
    else                      { in = i3; out = o3; }
    rt_body(in, out, D_MODEL, D_MODEL);
}

// ---------------------------------------------------------------------------
// Block reduction helper (256 threads)
// ---------------------------------------------------------------------------
__device__ __forceinline__ float blockReduceSum(float v) {
    __shared__ float sred[32];
    int lane = threadIdx.x & 31;
    int w    = threadIdx.x >> 5;
    #pragma unroll
    for (int o = 16; o > 0; o >>= 1) v += __shfl_xor_sync(0xffffffffu, v, o);
    if (lane == 0) sred[w] = v;
    __syncthreads();
    float r = (threadIdx.x < (blockDim.x >> 5)) ? sred[threadIdx.x] : 0.f;
    if (w == 0) {
        #pragma unroll
        for (int o = 4; o > 0; o >>= 1) r += __shfl_xor_sync(0xffffffffu, r, o);
        if (lane == 0) sred[0] = r;
    }
    __syncthreads();
    float out = sred[0];
    __syncthreads();
    return out;
}

// ---------------------------------------------------------------------------
// LayerNorm: one block per row. Output is tf32-rounded (feeds tensor cores).
// ---------------------------------------------------------------------------
__global__ __launch_bounds__(256)
void layernorm_kernel(const float* __restrict__ x, const float* __restrict__ g,
                      const float* __restrict__ b, float* __restrict__ out) {
    int row = blockIdx.x;
    int t   = threadIdx.x;
    const float* xr = x + (size_t)row * D_MODEL;
    float4 v = *(const float4*)(xr + t * 4);
    float sum = v.x + v.y + v.z + v.w;
    float mean = blockReduceSum(sum) * (1.f / (float)D_MODEL);
    float dx = v.x - mean, dy = v.y - mean, dz = v.z - mean, dw = v.w - mean;
    float sq = dx * dx + dy * dy + dz * dz + dw * dw;
    float var  = blockReduceSum(sq) * (1.f / (float)D_MODEL);
    float rstd = rsqrtf(var + 1e-6f);
    float4 gv = *(const float4*)(g + t * 4);
    float4 bv = *(const float4*)(b + t * 4);
    float4 o;
    o.x = round_tf32(dx * rstd * gv.x + bv.x);
    o.y = round_tf32(dy * rstd * gv.y + bv.y);
    o.z = round_tf32(dz * rstd * gv.z + bv.z);
    o.w = round_tf32(dw * rstd * gv.w + bv.w);
    *(float4*)(out + (size_t)row * D_MODEL + t * 4) = o;
}

// ---------------------------------------------------------------------------
// TF32 tensor-core GEMM (unchanged from round 10). 4 warps, warp tile 64x64.
// ---------------------------------------------------------------------------
#define BM 128
#define BN 128
#define GBK 16
#define GSTAGES 3
#define STAGE_BYTES (BM * GBK * 4)   // 8192

template <int EPI>
__device__ __forceinline__ void gemm_body(const float* __restrict__ A, const float* __restrict__ Wt,
                                          const float* __restrict__ bias, const float* __restrict__ res,
                                          float* __restrict__ C, int N, int K) {
    __shared__ unsigned As[GSTAGES][BM * GBK];   // 24 KB
    __shared__ unsigned Bs[GSTAGES][BN * GBK];   // 24 KB

    int tid  = threadIdx.x;          // 0..127
    int lane = tid & 31;
    int wid  = tid >> 5;             // 0..3
    int g    = lane >> 2;
    int tig  = lane & 3;

    int bm = blockIdx.y * BM;
    int bn = blockIdx.x * BN;
    int rowBase = (wid >> 1) * 64;
    int colBase = (wid & 1) * 64;

    float c[4][8][4];
    #pragma unroll
    for (int mt = 0; mt < 4; mt++)
        #pragma unroll
        for (int nt = 0; nt < 8; nt++)
            #pragma unroll
            for (int r = 0; r < 4; r++) c[mt][nt][r] = 0.f;

    int lrow = tid >> 2;
    int lc   = tid & 3;
    int lsw  = (lrow >> 1) & 3;
    int w0   = lrow * GBK + ((lc ^ lsw) << 2);

    unsigned aBase = smem_u32(&As[0][0]);
    unsigned bBase = smem_u32(&Bs[0][0]);

    const float* aS0 = A  + (size_t)(bm + lrow) * K + lc * 4;
    const float* bS0 = Wt + (size_t)(bn + lrow) * K + lc * 4;
    size_t rstep = (size_t)32 * K;

    unsigned baseA[4], baseB[4];
    #pragma unroll
    for (int mt = 0; mt < 4; mt++) {
        int r = rowBase + mt * 16 + (lane & 15);
        int h = lane >> 4;
        int s = (r >> 1) & 3;
        baseA[mt] = aBase + (unsigned)(r * GBK * 4)
                  + (unsigned)((((h ^ (s & 1)) << 4) | ((s >> 1) << 5)));
    }
    #pragma unroll
    for (int ntp = 0; ntp < 4; ntp++) {
        int r = colBase + ntp * 16 + ((lane >> 4) & 1) * 8 + (lane & 7);
        int h = (lane >> 3) & 1;
        int s = (r >> 1) & 3;
        baseB[ntp] = bBase + (unsigned)(r * GBK * 4)
                   + (unsigned)((((h ^ (s & 1)) << 4) | ((s >> 1) << 5)));
    }

    auto issue_tile = [&](int k0, int s) {
        unsigned aD = aBase + (unsigned)(s * STAGE_BYTES);
        unsigned bD = bBase + (unsigned)(s * STAGE_BYTES);
        #pragma unroll
        for (int i = 0; i < 4; i++) {
            unsigned wo = (unsigned)((w0 + i * 32 * GBK) * 4);
            cp_async16(aD + wo, aS0 + i * rstep + k0);
            cp_async16(bD + wo, bS0 + i * rstep + k0);
        }
    };

    int nIter = K / GBK;
    issue_tile(0, 0);      CP_COMMIT();
    issue_tile(GBK, 1);    CP_COMMIT();

    for (int it = 0; it < nIter; it++) {
        unsigned off = (unsigned)((it % GSTAGES) * STAGE_BYTES);

        CP_WAIT1();
        __syncthreads();

        #pragma unroll
        for (int ks = 0; ks < 2; ks++) {
            unsigned kx = (unsigned)(ks << 5);
            unsigned fa[4][4], fb[4][4];
            #pragma unroll
            for (int mt = 0; mt < 4; mt++)
                ldsm_x4(fa[mt][0], fa[mt][1], fa[mt][2], fa[mt][3],
                        (baseA[mt] + off) ^ kx);
            #pragma unroll
            for (int ntp = 0; ntp < 4; ntp++)
                ldsm_x4(fb[ntp][0], fb[ntp][1], fb[ntp][2], fb[ntp][3],
                        (baseB[ntp] + off) ^ kx);

            if (ks == 0) {
                if (it + 2 < nIter) issue_tile((it + 2) * GBK, (it + 2) % GSTAGES);
                CP_COMMIT();
            }

            #pragma unroll
            for (int mt = 0; mt < 4; mt++) {
                #pragma unroll
                for (int ntp = 0; ntp < 4; ntp++) {
                    int n0 = ntp * 2, n1 = ntp * 2 + 1;
                    mma_tf32(c[mt][n0][0], c[mt][n0][1], c[mt][n0][2], c[mt][n0][3],
                             fa[mt][0], fa[mt][1], fa[mt][2], fa[mt][3],
                             fb[ntp][0], fb[ntp][1]);
                    mma_tf32(c[mt][n1][0], c[mt][n1][1], c[mt][n1][2], c[mt][n1][3],
                             fa[mt][0], fa[mt][1], fa[mt][2], fa[mt][3],
                             fb[ntp][2], fb[ntp][3]);
                }
            }
        }
    }

    #pragma unroll
    for (int mt = 0; mt < 4; mt++) {
        #pragma unroll
        for (int half = 0; half < 2; half++) {
            size_t row = (size_t)(bm + rowBase + mt * 16 + g + half * 8);
            #pragma unroll
            for (int nt = 0; nt < 8; nt++) {
                int col = bn + colBase + nt * 8 + tig * 2;
                float v0 = c[mt][nt][half * 2 + 0];
                float v1 = c[mt][nt][half * 2 + 1];
                if (bias) {
                    float2 bb = *(const float2*)(bias + col);
                    v0 += bb.x; v1 += bb.y;
                }
                if (EPI == 0) { v0 = round_tf32(v0); v1 = round_tf32(v1); }
                if (EPI == 2) {
                    v0 = round_tf32(gelu_tanh(v0));
                    v1 = round_tf32(gelu_tanh(v1));
                }
                if (EPI == 1) {
                    const float2 rv = *(const float2*)(res + row * N + col);
                    v0 += rv.x; v1 += rv.y;
                }
                float2 o; o.x = v0; o.y = v1;
                *(float2*)(C + row * N + col) = o;
            }
        }
    }
}

template <int EPI>
__global__ __launch_bounds__(128, 2)
void gemm_tf32_kernel(const float* __restrict__ A, const float* __restrict__ Wt,
                      const float* __restrict__ bias, const float* __restrict__ res,
                      float* __restrict__ C, int N, int K) {
    gemm_body<EPI>(A, Wt, bias, res, C, N, K);
}

__global__ __launch_bounds__(128, 2)
void gemm_qkv_kernel(const float* __restrict__ A,
                     const float* __restrict__ Wq, const float* __restrict__ bq, float* __restrict__ q,
                     const float* __restrict__ Wk, const float* __restrict__ bk, float* __restrict__ k,
                     const float* __restrict__ Wv, const float* __restrict__ bvp, float* __restrict__ v) {
    const float* W; const float* bi; float* C;
    if (blockIdx.z == 0)      { W = Wq; bi = bq; C = q; }
    else if (blockIdx.z == 1) { W = Wk; bi = bk; C = k; }
    else                      { W = Wv; bi = bvp; C = v; }
    gemm_body<0>(A, W, bi, nullptr, C, D_MODEL, D_MODEL);
}

// ---------------------------------------------------------------------------
// Flash attention v2 (causal), tf32 tensor cores.
// FB_Q=128 (8 warps x 16 rows) amortizes each 64-key K/V tile over 2x queries.
// Q/K/V pre-rounded tf32 -> raw uint4 staging. Per-row math identical to the
// FB_Q=64 version (same per-tile k-order) => bit-identical results.
// Dynamic smem: KsPs[128][68] (K rows 0..63; P all 128 rows) + Vs[64][72].
// ---------------------------------------------------------------------------
#define FB_Q 128
#define FB_K 64
#define KS_ST 68
#define VS_ST 72
#define FLASH_THREADS 256
#define FLASH_SMEM (FB_Q * KS_ST * 4 + FB_K * VS_ST * 4)   // 34816+18432 = 53248

__global__ __launch_bounds__(FLASH_THREADS)
void flash_mma_kernel(const float* __restrict__ Q, const float* __restrict__ K,
                      const float* __restrict__ V, float* __restrict__ O) {
    extern __shared__ unsigned fsm[];
    unsigned (*KsPs)[KS_ST] = (unsigned (*)[KS_ST])fsm;              // [FB_Q][68]
    unsigned (*Vs)[VS_ST]   = (unsigned (*)[VS_ST])(fsm + FB_Q * KS_ST);  // [FB_K][72]

    int qt   = blockIdx.x;
    int bh   = blockIdx.y;
    int b    = bh >> 4;
    int h    = bh & 15;
    int tid  = threadIdx.x;
    int lane = tid & 31;
    int w    = tid >> 5;          // 0..7
    int g    = lane >> 2;
    int tig  = lane & 3;

    size_t base = ((size_t)b * SEQ) * D_MODEL + h * D_HEAD;

    // ---- stage Q tile (128x64, raw copy) ----
    #pragma unroll
    for (int l = 0; l < 8; l++) {
        int f  = tid + l * FLASH_THREADS;
        int r  = f >> 4;
        int c4 = (f & 15) * 4;
        uint4 v = *(const uint4*)(Q + base + (size_t)(qt * FB_Q + r) * D_MODEL + c4);
        *(uint4*)(&KsPs[r][c4]) = v;
    }
    __syncthreads();
    unsigned aq[8][4];
    #pragma unroll
    for (int ks = 0; ks < 8; ks++) {
        int r0 = w * 16 + g;
        aq[ks][0] = KsPs[r0][ks * 8 + tig];
        aq[ks][1] = KsPs[r0 + 8][ks * 8 + tig];
        aq[ks][2] = KsPs[r0][ks * 8 + tig + 4];
        aq[ks][3] = KsPs[r0 + 8][ks * 8 + tig + 4];
    }
    __syncthreads();

    float o[8][4];
    #pragma unroll
    for (int nt = 0; nt < 8; nt++)
        #pragma unroll
        for (int r = 0; r < 4; r++) o[nt][r] = 0.f;

    float m0 = -1e30f, m1 = -1e30f, l0 = 0.f, l1 = 0.f;
    int qrow0 = qt * FB_Q + w * 16 + g;
    int qrow1 = qrow0 + 8;
    const float SCL = 0.125f * 1.4426950408889634f;

    int ntile = (qt + 1) * (FB_Q / FB_K);
    for (int kt = 0; kt < ntile; kt++) {
        // ---- load K,V tile (64x64 each): raw uint4 copies ----
        #pragma unroll
        for (int l = 0; l < 4; l++) {
            int f  = tid + l * FLASH_THREADS;
            int r  = f >> 4;
            int c4 = (f & 15) * 4;
            size_t ga = base + (size_t)(kt * FB_K + r) * D_MODEL + c4;
            uint4 kv = *(const uint4*)(K + ga);
            uint4 vv = *(const uint4*)(V + ga);
            *(uint4*)(&KsPs[r][c4]) = kv;
            *(uint4*)(&Vs[r][c4])   = vv;
        }
        __syncthreads();

        float s[8][4];
        #pragma unroll
        for (int nt = 0; nt < 8; nt++)
            #pragma unroll
            for (int r = 0; r < 4; r++) s[nt][r] = 0.f;
        #pragma unroll
        for (int ks = 0; ks < 8; ks++) {
            #pragma unroll
            for (int nt = 0; nt < 8; nt++) {
                unsigned b0 = KsPs[nt * 8 + g][ks * 8 + tig];
                unsigned b1 = KsPs[nt * 8 + g][ks * 8 + tig + 4];
                mma_tf32(s[nt][0], s[nt][1], s[nt][2], s[nt][3],
                         aq[ks][0], aq[ks][1], aq[ks][2], aq[ks][3], b0, b1);
            }
        }
        __syncthreads();   // all warps done reading K before P overwrites it

        bool diag = (kt * FB_K + FB_K - 1) > qrow0;
        #pragma unroll
        for (int nt = 0; nt < 8; nt++) {
            int kc = kt * FB_K + nt * 8 + tig * 2;
            s[nt][0] *= SCL; s[nt][1] *= SCL; s[nt][2] *= SCL; s[nt][3] *= SCL;
            if (diag) {
                if (kc     > qrow0) s[nt][0] = -1e30f;
                if (kc + 1 > qrow0) s[nt][1] = -1e30f;
                if (kc     > qrow1) s[nt][2] = -1e30f;
                if (kc + 1 > qrow1) s[nt][3] = -1e30f;
            }
        }

        float rm0 = -1e30f, rm1 = -1e30f;
        #pragma unroll
        for (int nt = 0; nt < 8; nt++) {
            rm0 = fmaxf(rm0, fmaxf(s[nt][0], s[nt][1]));
            rm1 = fmaxf(rm1, fmaxf(s[nt][2], s[nt][3]));
        }
        rm0 = fmaxf(rm0, __shfl_xor_sync(0xffffffffu, rm0, 1));
        rm0 = fmaxf(rm0, __shfl_xor_sync(0xffffffffu, rm0, 2));
        rm1 = fmaxf(rm1, __shfl_xor_sync(0xffffffffu, rm1, 1));
        rm1 = fmaxf(rm1, __shfl_xor_sync(0xffffffffu, rm1, 2));
        float mn0 = fmaxf(m0, rm0), mn1 = fmaxf(m1, rm1);
        float sc0 = exp2f(m0 - mn0), sc1 = exp2f(m1 - mn1);
        m0 = mn0; m1 = mn1;

        float ls0 = 0.f, ls1 = 0.f;
        #pragma unroll
        for (int nt = 0; nt < 8; nt++) {
            s[nt][0] = exp2f(s[nt][0] - mn0);
            s[nt][1] = exp2f(s[nt][1] - mn0);
            s[nt][2] = exp2f(s[nt][2] - mn1);
            s[nt][3] = exp2f(s[nt][3] - mn1);
            ls0 += s[nt][0] + s[nt][1];
            ls1 += s[nt][2] + s[nt][3];
        }
        ls0 += __shfl_xor_sync(0xffffffffu, ls0, 1);
        ls0 += __shfl_xor_sync(0xffffffffu, ls0, 2);
        ls1 += __shfl_xor_sync(0xffffffffu, ls1, 1);
        ls1 += __shfl_xor_sync(0xffffffffu, ls1, 2);
        l0 = l0 * sc0 + ls0;
        l1 = l1 * sc1 + ls1;

        #pragma unroll
        for (int nt = 0; nt < 8; nt++) {
            o[nt][0] *= sc0; o[nt][1] *= sc0;
            o[nt][2] *= sc1; o[nt][3] *= sc1;
        }

        // ---- write P into warp-private rows of KsPs (tf32) ----
        {
            int r0 = w * 16 + g;
            #pragma unroll
            for (int nt = 0; nt < 8; nt++) {
                int cc = nt * 8 + tig * 2;
                KsPs[r0][cc]     = f2tf32(s[nt][0]);
                KsPs[r0][cc + 1] = f2tf32(s[nt][1]);
                KsPs[r0 + 8][cc]     = f2tf32(s[nt][2]);
                KsPs[r0 + 8][cc + 1] = f2tf32(s[nt][3]);
            }
        }
        __syncwarp();

        // ---- O += P @ V ----
        #pragma unroll
        for (int ks = 0; ks < 8; ks++) {
            int r0 = w * 16 + g;
            unsigned ap0 = KsPs[r0][ks * 8 + tig];
            unsigned ap1 = KsPs[r0 + 8][ks * 8 + tig];
            unsigned ap2 = KsPs[r0][ks * 8 + tig + 4];
            unsigned ap3 = KsPs[r0 + 8][ks * 8 + tig + 4];
            #pragma unroll
            for (int nt = 0; nt < 8; nt++) {
                unsigned b0 = Vs[ks * 8 + tig][nt * 8 + g];
                unsigned b1 = Vs[ks * 8 + tig + 4][nt * 8 + g];
                mma_tf32(o[nt][0], o[nt][1], o[nt][2], o[nt][3],
                         ap0, ap1, ap2, ap3, b0, b1);
            }
        }
        __syncthreads();   // everyone done with K(P)/V before next tile load
    }

    float inv0 = 1.f / l0, inv1 = 1.f / l1;
    #pragma unroll
    for (int nt = 0; nt < 8; nt++) {
        int col = nt * 8 + tig * 2;
        float2 r0; r0.x = round_tf32(o[nt][0] * inv0); r0.y = round_tf32(o[nt][1] * inv0);
        float2 r1; r1.x = round_tf32(o[nt][2] * inv1); r1.y = round_tf32(o[nt][3] * inv1);
        *(float2*)(O + base + (size_t)qrow0 * D_MODEL + col) = r0;
        *(float2*)(O + base + (size_t)qrow1 * D_MODEL + col) = r1;
    }
}

// ---------------------------------------------------------------------------
// Launch
// ---------------------------------------------------------------------------
extern "C" void kernel_launch(void* const* d_in, const int* in_sizes, int n_in,
                              void* d_out, int out_size) {
    const float* x   = (const float*)d_in[0];
    const float* Wq  = (const float*)d_in[1];
    const float* bq  = (const float*)d_in[2];
    const float* Wk  = (const float*)d_in[3];
    const float* bk  = (const float*)d_in[4];
    const float* Wv  = (const float*)d_in[5];
    const float* bv  = (const float*)d_in[6];
    const float* Wo  = (const float*)d_in[7];
    const float* W1  = (const float*)d_in[8];
    const float* b1  = (const float*)d_in[9];
    const float* W2  = (const float*)d_in[10];
    const float* b2  = (const float*)d_in[11];
    const float* g1  = (const float*)d_in[12];
    const float* be1 = (const float*)d_in[13];
    const float* g2  = (const float*)d_in[14];
    const float* be2 = (const float*)d_in[15];
    float* out = (float*)d_out;

    float *ln, *q, *k, *v, *attn, *x1, *h;
    float *wq, *wk, *wv, *wo, *w1, *w2;
    cudaGetSymbolAddress((void**)&ln,   g_ln);
    cudaGetSymbolAddress((void**)&q,    g_q);
    cudaGetSymbolAddress((void**)&k,    g_k);
    cudaGetSymbolAddress((void**)&v,    g_v);
    cudaGetSymbolAddress((void**)&attn, g_attn);
    cudaGetSymbolAddress((void**)&x1,   g_x1);
    cudaGetSymbolAddress((void**)&h,    g_h);
    cudaGetSymbolAddress((void**)&wq,   g_wq);
    cudaGetSymbolAddress((void**)&wk,   g_wk);
    cudaGetSymbolAddress((void**)&wv,   g_wv);
    cudaGetSymbolAddress((void**)&wo,   g_wo);
    cudaGetSymbolAddress((void**)&w1,   g_w1);
    cudaGetSymbolAddress((void**)&w2,   g_w2);

    cudaFuncSetAttribute(flash_mma_kernel,
                         cudaFuncAttributeMaxDynamicSharedMemorySize, FLASH_SMEM);

    dim3 gemm_d(D_MODEL / BN, T_TOKENS / BM);        // (8, 64)
    dim3 gemm_qkv(D_MODEL / BN, T_TOKENS / BM, 3);   // (8, 64, 3)
    dim3 gemm_ff1(D_FF / BN, T_TOKENS / BM);         // (32, 64)

    // 0) round + transpose weights (Wt[n][k]); 4 DxD batched + W1 + W2
    dim3 tB(32, 8);
    dim3 tDD4(D_MODEL / 32, D_MODEL / 32, 4);
    dim3 tDF(D_FF / 32, D_MODEL / 32);
    dim3 tFD(D_MODEL / 32, D_FF / 32);
    round_transpose4_kernel<<<tDD4, tB>>>(Wq, Wk, Wv, Wo, wq, wk, wv, wo);
    round_transpose_kernel<<<tDF, tB>>>(W1, w1, D_MODEL, D_FF);
    round_transpose_kernel<<<tFD, tB>>>(W2, w2, D_FF, D_MODEL);

    // 1) ln1 = LN(x; g1, beta1)   [tf32-rounded output]
    layernorm_kernel<<<T_TOKENS, 256>>>(x, g1, be1, ln);
    // 2) Q,K,V = ln1 @ W* + b*   (fused launch; outputs tf32-rounded)
    gemm_qkv_kernel<<<gemm_qkv, 128>>>(ln, wq, bq, q, wk, bk, k, wv, bv, v);
    // 3) causal flash attention (FB_Q=128; tf32-rounded output)
    flash_mma_kernel<<<dim3(SEQ / FB_Q, BATCH * N_HEADS), FLASH_THREADS, FLASH_SMEM>>>(q, k, v, attn);
    // 4) x1 = x + attn @ Wo      (no bias on o-proj; full fp32 residual)
    gemm_tf32_kernel<1><<<gemm_d, 128>>>(attn, wo, nullptr, x, x1, D_MODEL, D_MODEL);
    // 5) ln2 = LN(x1; g2, beta2) [tf32-rounded output]
    layernorm_kernel<<<T_TOKENS, 256>>>(x1, g2, be2, ln);
    // 6) h = gelu(ln2 @ W1 + b1) [tf32-rounded output]
    gemm_tf32_kernel<2><<<gemm_ff1, 128>>>(ln, w1, b1, nullptr, h, D_FF, D_MODEL);
    // 7) out = x1 + h @ W2 + b2  (full fp32 output)
    gemm_tf32_kernel<1><<<gemm_d, 128>>>(h, w2, b2, x1, out, D_MODEL, D_FF);
}

// round 12
// speedup vs baseline: 1.0515x; 1.0515x over previous
#include <cuda_runtime.h>
#include <cuda_bf16.h>
#include <math.h>

// ---------------------------------------------------------------------------
// Problem constants
// ---------------------------------------------------------------------------
#define T_TOKENS 8192   // B*S = 4*2048
#define D_MODEL  1024
#define D_FF     4096
#define N_HEADS  16
#define D_HEAD   64
#define SEQ      2048
#define BATCH    4

// ---------------------------------------------------------------------------
// Scratch (device globals; no allocation allowed)
// ---------------------------------------------------------------------------
__device__ float g_ln  [T_TOKENS * D_MODEL];
__device__ float g_q   [T_TOKENS * D_MODEL];
__device__ float g_k   [T_TOKENS * D_MODEL];
__device__ float g_v   [T_TOKENS * D_MODEL];
__device__ float g_attn[T_TOKENS * D_MODEL];
__device__ float g_x1  [T_TOKENS * D_MODEL];
__device__ float g_h   [T_TOKENS * D_FF];
// tf32-rounded AND transposed weights: Wt[n][k]
__device__ float g_wq[D_MODEL * D_MODEL];
__device__ float g_wk[D_MODEL * D_MODEL];
__device__ float g_wv[D_MODEL * D_MODEL];
__device__ float g_wo[D_MODEL * D_MODEL];
__device__ float g_w1[D_MODEL * D_FF];
__device__ float g_w2[D_FF * D_MODEL];

// ---------------------------------------------------------------------------
// Common helpers
// ---------------------------------------------------------------------------
__device__ __forceinline__ unsigned f2tf32(float x) {
    unsigned r;
    asm("cvt.rna.tf32.f32 %0, %1;" : "=r"(r) : "f"(x));
    return r;
}

__device__ __forceinline__ float round_tf32(float x) {
    return __uint_as_float(f2tf32(x));
}

__device__ __forceinline__ unsigned smem_u32(const void* p) {
    return (unsigned)__cvta_generic_to_shared(p);
}

__device__ __forceinline__ void ldsm_x4(unsigned& r0, unsigned& r1,
                                        unsigned& r2, unsigned& r3, unsigned addr) {
    asm volatile("ldmatrix.sync.aligned.m8n8.x4.shared.b16 {%0,%1,%2,%3}, [%4];"
                 : "=r"(r0), "=r"(r1), "=r"(r2), "=r"(r3) : "r"(addr));
}

__device__ __forceinline__ void mma_tf32(float& c0, float& c1, float& c2, float& c3,
                                         unsigned a0, unsigned a1, unsigned a2, unsigned a3,
                                         unsigned b0, unsigned b1) {
    asm volatile(
        "mma.sync.aligned.m16n8k8.row.col.f32.tf32.tf32.f32 "
        "{%0,%1,%2,%3}, {%4,%5,%6,%7}, {%8,%9}, {%0,%1,%2,%3};"
        : "+f"(c0), "+f"(c1), "+f"(c2), "+f"(c3)
        : "r"(a0), "r"(a1), "r"(a2), "r"(a3), "r"(b0), "r"(b1));
}

__device__ __forceinline__ void cp_async16(unsigned dst, const void* src) {
    asm volatile("cp.async.ca.shared.global [%0], [%1], 16;" :: "r"(dst), "l"(src));
}
#define CP_COMMIT()  asm volatile("cp.async.commit_group;")
#define CP_WAIT1()   asm volatile("cp.async.wait_group 1;")
#define CP_WAIT0()   asm volatile("cp.async.wait_group 0;")

__device__ __forceinline__ float gelu_tanh(float x) {
    float x3 = x * x * x;
    return 0.5f * x * (1.f + tanhf(0.7978845608028654f * (x + 0.044715f * x3)));
}

// ---------------------------------------------------------------------------
// Weight prep: tf32-round + transpose.  in: W[K,N]  out: Wt[N,K] (rounded)
// ---------------------------------------------------------------------------
__device__ __forceinline__ void rt_body(const float* __restrict__ in,
                                        float* __restrict__ out, int K, int N) {
    __shared__ float tile[32][33];
    int n0 = blockIdx.x * 32;
    int k0 = blockIdx.y * 32;
    #pragma unroll
    for (int i = threadIdx.y; i < 32; i += 8)
        tile[i][threadIdx.x] = in[(size_t)(k0 + i) * N + n0 + threadIdx.x];
    __syncthreads();
    #pragma unroll
    for (int i = threadIdx.y; i < 32; i += 8)
        out[(size_t)(n0 + i) * K + k0 + threadIdx.x] = round_tf32(tile[threadIdx.x][i]);
}

__global__ __launch_bounds__(256)
void round_transpose_kernel(const float* __restrict__ in, float* __restrict__ out,
                            int K, int N) {
    rt_body(in, out, K, N);
}

__global__ __launch_bounds__(256)
void round_transpose4_kernel(const float* __restrict__ i0, const float* __restrict__ i1,
                             const float* __restrict__ i2, const float* __restrict__ i3,
                             float* __restrict__ o0, float* __restrict__ o1,
                             float* __restrict__ o2, float* __restrict__ o3) {
    const float* in; float* out;
    if (blockIdx.z == 0)      { in = i0; out = o0; }
    else if (blockIdx.z == 1) { in = i1; out = o1; }
    else if (blockIdx.z == 2) { in = i2; out = o2; }
    else                      { in = i3; out = o3; }
    rt_body(in, out, D_MODEL, D_MODEL);
}

// ---------------------------------------------------------------------------
// Block reduction helper (256 threads)
// ---------------------------------------------------------------------------
__device__ __forceinline__ float blockReduceSum(float v) {
    __shared__ float sred[32];
    int lane = threadIdx.x & 31;
    int w    = threadIdx.x >> 5;
    #pragma unroll
    for (int o = 16; o > 0; o >>= 1) v += __shfl_xor_sync(0xffffffffu, v, o);
    if (lane == 0) sred[w] = v;
    __syncthreads();
    float r = (threadIdx.x < (blockDim.x >> 5)) ? sred[threadIdx.x] : 0.f;
    if (w == 0) {
        #pragma unroll
        for (int o = 4; o > 0; o >>= 1) r += __shfl_xor_sync(0xffffffffu, r, o);
        if (lane == 0) sred[0] = r;
    }
    __syncthreads();
    float out = sred[0];
    __syncthreads();
    return out;
}

// ---------------------------------------------------------------------------
// LayerNorm: one block per row. Output is tf32-rounded (feeds tensor cores).
// ---------------------------------------------------------------------------
__global__ __launch_bounds__(256)
void layernorm_kernel(const float* __restrict__ x, const float* __restrict__ g,
                      const float* __restrict__ b, float* __restrict__ out) {
    int row = blockIdx.x;
    int t   = threadIdx.x;
    const float* xr = x + (size_t)row * D_MODEL;
    float4 v = *(const float4*)(xr + t * 4);
    float sum = v.x + v.y + v.z + v.w;
    float mean = blockReduceSum(sum) * (1.f / (float)D_MODEL);
    float dx = v.x - mean, dy = v.y - mean, dz = v.z - mean, dw = v.w - mean;
    float sq = dx * dx + dy * dy + dz * dz + dw * dw;
    float var  = blockReduceSum(sq) * (1.f / (float)D_MODEL);
    float rstd = rsqrtf(var + 1e-6f);
    float4 gv = *(const float4*)(g + t * 4);
    float4 bv = *(const float4*)(b + t * 4);
    float4 o;
    o.x = round_tf32(dx * rstd * gv.x + bv.x);
    o.y = round_tf32(dy * rstd * gv.y + bv.y);
    o.z = round_tf32(dz * rstd * gv.z + bv.z);
    o.w = round_tf32(dw * rstd * gv.w + bv.w);
    *(float4*)(out + (size_t)row * D_MODEL + t * 4) = o;
}

// ---------------------------------------------------------------------------
// TF32 tensor-core GEMM (unchanged from round 10). 4 warps, warp tile 64x64.
// ---------------------------------------------------------------------------
#define BM 128
#define BN 128
#define GBK 16
#define GSTAGES 3
#define STAGE_BYTES (BM * GBK * 4)   // 8192

template <int EPI>
__device__ __forceinline__ void gemm_body(const float* __restrict__ A, const float* __restrict__ Wt,
                                          const float* __restrict__ bias, const float* __restrict__ res,
                                          float* __restrict__ C, int N, int K) {
    __shared__ unsigned As[GSTAGES][BM * GBK];   // 24 KB
    __shared__ unsigned Bs[GSTAGES][BN * GBK];   // 24 KB

    int tid  = threadIdx.x;          // 0..127
    int lane = tid & 31;
    int wid  = tid >> 5;             // 0..3
    int g    = lane >> 2;
    int tig  = lane & 3;

    int bm = blockIdx.y * BM;
    int bn = blockIdx.x * BN;
    int rowBase = (wid >> 1) * 64;
    int colBase = (wid & 1) * 64;

    float c[4][8][4];
    #pragma unroll
    for (int mt = 0; mt < 4; mt++)
        #pragma unroll
        for (int nt = 0; nt < 8; nt++)
            #pragma unroll
            for (int r = 0; r < 4; r++) c[mt][nt][r] = 0.f;

    int lrow = tid >> 2;
    int lc   = tid & 3;
    int lsw  = (lrow >> 1) & 3;
    int w0   = lrow * GBK + ((lc ^ lsw) << 2);

    unsigned aBase = smem_u32(&As[0][0]);
    unsigned bBase = smem_u32(&Bs[0][0]);

    const float* aS0 = A  + (size_t)(bm + lrow) * K + lc * 4;
    const float* bS0 = Wt + (size_t)(bn + lrow) * K + lc * 4;
    size_t rstep = (size_t)32 * K;

    unsigned baseA[4], baseB[4];
    #pragma unroll
    for (int mt = 0; mt < 4; mt++) {
        int r = rowBase + mt * 16 + (lane & 15);
        int h = lane >> 4;
        int s = (r >> 1) & 3;
        baseA[mt] = aBase + (unsigned)(r * GBK * 4)
                  + (unsigned)((((h ^ (s & 1)) << 4) | ((s >> 1) << 5)));
    }
    #pragma unroll
    for (int ntp = 0; ntp < 4; ntp++) {
        int r = colBase + ntp * 16 + ((lane >> 4) & 1) * 8 + (lane & 7);
        int h = (lane >> 3) & 1;
        int s = (r >> 1) & 3;
        baseB[ntp] = bBase + (unsigned)(r * GBK * 4)
                   + (unsigned)((((h ^ (s & 1)) << 4) | ((s >> 1) << 5)));
    }

    auto issue_tile = [&](int k0, int s) {
        unsigned aD = aBase + (unsigned)(s * STAGE_BYTES);
        unsigned bD = bBase + (unsigned)(s * STAGE_BYTES);
        #pragma unroll
        for (int i = 0; i < 4; i++) {
            unsigned wo = (unsigned)((w0 + i * 32 * GBK) * 4);
            cp_async16(aD + wo, aS0 + i * rstep + k0);
            cp_async16(bD + wo, bS0 + i * rstep + k0);
        }
    };

    int nIter = K / GBK;
    issue_tile(0, 0);      CP_COMMIT();
    issue_tile(GBK, 1);    CP_COMMIT();

    for (int it = 0; it < nIter; it++) {
        unsigned off = (unsigned)((it % GSTAGES) * STAGE_BYTES);

        CP_WAIT1();
        __syncthreads();

        #pragma unroll
        for (int ks = 0; ks < 2; ks++) {
            unsigned kx = (unsigned)(ks << 5);
            unsigned fa[4][4], fb[4][4];
            #pragma unroll
            for (int mt = 0; mt < 4; mt++)
                ldsm_x4(fa[mt][0], fa[mt][1], fa[mt][2], fa[mt][3],
                        (baseA[mt] + off) ^ kx);
            #pragma unroll
            for (int ntp = 0; ntp < 4; ntp++)
                ldsm_x4(fb[ntp][0], fb[ntp][1], fb[ntp][2], fb[ntp][3],
                        (baseB[ntp] + off) ^ kx);

            if (ks == 0) {
                if (it + 2 < nIter) issue_tile((it + 2) * GBK, (it + 2) % GSTAGES);
                CP_COMMIT();
            }

            #pragma unroll
            for (int mt = 0; mt < 4; mt++) {
                #pragma unroll
                for (int ntp = 0; ntp < 4; ntp++) {
                    int n0 = ntp * 2, n1 = ntp * 2 + 1;
                    mma_tf32(c[mt][n0][0], c[mt][n0][1], c[mt][n0][2], c[mt][n0][3],
                             fa[mt][0], fa[mt][1], fa[mt][2], fa[mt][3],
                             fb[ntp][0], fb[ntp][1]);
                    mma_tf32(c[mt][n1][0], c[mt][n1][1], c[mt][n1][2], c[mt][n1][3],
                             fa[mt][0], fa[mt][1], fa[mt][2], fa[mt][3],
                             fb[ntp][2], fb[ntp][3]);
                }
            }
        }
    }

    #pragma unroll
    for (int mt = 0; mt < 4; mt++) {
        #pragma unroll
        for (int half = 0; half < 2; half++) {
            size_t row = (size_t)(bm + rowBase + mt * 16 + g + half * 8);
            #pragma unroll
            for (int nt = 0; nt < 8; nt++) {
                int col = bn + colBase + nt * 8 + tig * 2;
                float v0 = c[mt][nt][half * 2 + 0];
                float v1 = c[mt][nt][half * 2 + 1];
                if (bias) {
                    float2 bb = *(const float2*)(bias + col);
                    v0 += bb.x; v1 += bb.y;
                }
                if (EPI == 0) { v0 = round_tf32(v0); v1 = round_tf32(v1); }
                if (EPI == 2) {
                    v0 = round_tf32(gelu_tanh(v0));
                    v1 = round_tf32(gelu_tanh(v1));
                }
                if (EPI == 1) {
                    const float2 rv = *(const float2*)(res + row * N + col);
                    v0 += rv.x; v1 += rv.y;
                }
                float2 o; o.x = v0; o.y = v1;
                *(float2*)(C + row * N + col) = o;
            }
        }
    }
}

template <int EPI>
__global__ __launch_bounds__(128, 2)
void gemm_tf32_kernel(const float* __restrict__ A, const float* __restrict__ Wt,
                      const float* __restrict__ bias, const float* __restrict__ res,
                      float* __restrict__ C, int N, int K) {
    gemm_body<EPI>(A, Wt, bias, res, C, N, K);
}

__global__ __launch_bounds__(128, 2)
void gemm_qkv_kernel(const float* __restrict__ A,
                     const float* __restrict__ Wq, const float* __restrict__ bq, float* __restrict__ q,
                     const float* __restrict__ Wk, const float* __restrict__ bk, float* __restrict__ k,
                     const float* __restrict__ Wv, const float* __restrict__ bvp, float* __restrict__ v) {
    const float* W; const float* bi; float* C;
    if (blockIdx.z == 0)      { W = Wq; bi = bq; C = q; }
    else if (blockIdx.z == 1) { W = Wk; bi = bk; C = k; }
    else                      { W = Wv; bi = bvp; C = v; }
    gemm_body<0>(A, W, bi, nullptr, C, D_MODEL, D_MODEL);
}

// ---------------------------------------------------------------------------
// Flash attention v2 (causal), tf32 tensor cores. FB_Q=64, 128 threads.
// K/V double-buffered via cp.async (tile kt+1 streams during tile kt compute);
// dedicated P buffer (no K alias) -> 2 barriers/tile instead of 3.
// Q/K/V pre-rounded tf32 (raw staging). Math identical to round 10
// (same per-tile k-order) => bit-identical results.
// Dynamic smem layout (words):
//   K0[64*68] K1[64*68] V0[64*72] V1[64*72] P[64*68]   = 22272 w = 89088 B
// ---------------------------------------------------------------------------
#define FB_Q 64
#define FB_K 64
#define KS_ST 68
#define VS_ST 72
#define FK_W (FB_K * KS_ST)      // 4352 words per K buffer
#define FV_W (FB_K * VS_ST)      // 4608 words per V buffer
#define FOFF_K0 0
#define FOFF_K1 (FK_W)
#define FOFF_V0 (2 * FK_W)
#define FOFF_V1 (2 * FK_W + FV_W)
#define FOFF_P  (2 * FK_W + 2 * FV_W)
#define FLASH_SMEM ((2 * FK_W + 2 * FV_W + FK_W) * 4)   // 89088 bytes

__global__ __launch_bounds__(128)
void flash_mma_kernel(const float* __restrict__ Q, const float* __restrict__ K,
                      const float* __restrict__ V, float* __restrict__ O) {
    extern __shared__ unsigned fsm[];
    unsigned sBase = smem_u32(fsm);

    int qt   = blockIdx.x;
    int bh   = blockIdx.y;
    int b    = bh >> 4;
    int h    = bh & 15;
    int tid  = threadIdx.x;
    int lane = tid & 31;
    int w    = tid >> 5;
    int g    = lane >> 2;
    int tig  = lane & 3;

    size_t base = ((size_t)b * SEQ) * D_MODEL + h * D_HEAD;

    // per-thread staging coords: f = tid + l*128 -> row f>>4, chunk (f&15)
    // (rows 0..63, 16 uint4 chunks per row)
    // cp.async K/V tile issue into buffer `buf`
    auto issue_kv = [&](int kt, int buf) {
        unsigned kD = sBase + (unsigned)((buf ? FOFF_K1 : FOFF_K0) * 4);
        unsigned vD = sBase + (unsigned)((buf ? FOFF_V1 : FOFF_V0) * 4);
        #pragma unroll
        for (int l = 0; l < 8; l++) {
            int f  = tid + l * 128;
            int r  = f >> 4;
            int c4 = (f & 15) * 4;
            size_t ga = base + (size_t)(kt * FB_K + r) * D_MODEL + c4;
            cp_async16(kD + (unsigned)((r * KS_ST + c4) * 4), K + ga);
            cp_async16(vD + (unsigned)((r * VS_ST + c4) * 4), V + ga);
        }
        CP_COMMIT();
    };

    int ntile = qt + 1;
    issue_kv(0, 0);   // tile 0 in flight while we stage Q

    // ---- stage Q tile (64x64, raw copy) into P buffer, extract fragments ----
    unsigned (*Pb)[KS_ST] = (unsigned (*)[KS_ST])(fsm + FOFF_P);
    #pragma unroll
    for (int l = 0; l < 8; l++) {
        int f  = tid + l * 128;
        int r  = f >> 4;
        int c4 = (f & 15) * 4;
        uint4 v = *(const uint4*)(Q + base + (size_t)(qt * FB_Q + r) * D_MODEL + c4);
        *(uint4*)(&Pb[r][c4]) = v;
    }
    __syncthreads();
    unsigned aq[8][4];
    #pragma unroll
    for (int ks = 0; ks < 8; ks++) {
        int r0 = w * 16 + g;
        aq[ks][0] = Pb[r0][ks * 8 + tig];
        aq[ks][1] = Pb[r0 + 8][ks * 8 + tig];
        aq[ks][2] = Pb[r0][ks * 8 + tig + 4];
        aq[ks][3] = Pb[r0 + 8][ks * 8 + tig + 4];
    }
    __syncthreads();   // everyone has Q fragments before P is reused

    float o[8][4];
    #pragma unroll
    for (int nt = 0; nt < 8; nt++)
        #pragma unroll
        for (int r = 0; r < 4; r++) o[nt][r] = 0.f;

    float m0 = -1e30f, m1 = -1e30f, l0 = 0.f, l1 = 0.f;
    int qrow0 = qt * FB_Q + w * 16 + g;
    int qrow1 = qrow0 + 8;
    const float SCL = 0.125f * 1.4426950408889634f;

    for (int kt = 0; kt < ntile; kt++) {
        int buf = kt & 1;
        unsigned (*Kb)[KS_ST] = (unsigned (*)[KS_ST])(fsm + (buf ? FOFF_K1 : FOFF_K0));
        unsigned (*Vb)[VS_ST] = (unsigned (*)[VS_ST])(fsm + (buf ? FOFF_V1 : FOFF_V0));

        // prefetch next tile into the other buffer, then wait for this tile
        if (kt + 1 < ntile) { issue_kv(kt + 1, 1 - buf); CP_WAIT1(); }
        else                { CP_WAIT0(); }
        __syncthreads();   // tile kt visible to all warps

        // ---- S = Q @ K^T ----
        float s[8][4];
        #pragma unroll
        for (int nt = 0; nt < 8; nt++)
            #pragma unroll
            for (int r = 0; r < 4; r++) s[nt][r] = 0.f;
        #pragma unroll
        for (int ks = 0; ks < 8; ks++) {
            #pragma unroll
            for (int nt = 0; nt < 8; nt++) {
                unsigned b0 = Kb[nt * 8 + g][ks * 8 + tig];
                unsigned b1 = Kb[nt * 8 + g][ks * 8 + tig + 4];
                mma_tf32(s[nt][0], s[nt][1], s[nt][2], s[nt][3],
                         aq[ks][0], aq[ks][1], aq[ks][2], aq[ks][3], b0, b1);
            }
        }

        // ---- scale + causal mask ----
        bool diag = (kt == qt);
        #pragma unroll
        for (int nt = 0; nt < 8; nt++) {
            int kc = kt * FB_K + nt * 8 + tig * 2;
            s[nt][0] *= SCL; s[nt][1] *= SCL; s[nt][2] *= SCL; s[nt][3] *= SCL;
            if (diag) {
                if (kc     > qrow0) s[nt][0] = -1e30f;
                if (kc + 1 > qrow0) s[nt][1] = -1e30f;
                if (kc     > qrow1) s[nt][2] = -1e30f;
                if (kc + 1 > qrow1) s[nt][3] = -1e30f;
            }
        }

        // ---- online softmax (log2 domain) ----
        float rm0 = -1e30f, rm1 = -1e30f;
        #pragma unroll
        for (int nt = 0; nt < 8; nt++) {
            rm0 = fmaxf(rm0, fmaxf(s[nt][0], s[nt][1]));
            rm1 = fmaxf(rm1, fmaxf(s[nt][2], s[nt][3]));
        }
        rm0 = fmaxf(rm0, __shfl_xor_sync(0xffffffffu, rm0, 1));
        rm0 = fmaxf(rm0, __shfl_xor_sync(0xffffffffu, rm0, 2));
        rm1 = fmaxf(rm1, __shfl_xor_sync(0xffffffffu, rm1, 1));
        rm1 = fmaxf(rm1, __shfl_xor_sync(0xffffffffu, rm1, 2));
        float mn0 = fmaxf(m0, rm0), mn1 = fmaxf(m1, rm1);
        float sc0 = exp2f(m0 - mn0), sc1 = exp2f(m1 - mn1);
        m0 = mn0; m1 = mn1;

        float ls0 = 0.f, ls1 = 0.f;
        #pragma unroll
        for (int nt = 0; nt < 8; nt++) {
            s[nt][0] = exp2f(s[nt][0] - mn0);
            s[nt][1] = exp2f(s[nt][1] - mn0);
            s[nt][2] = exp2f(s[nt][2] - mn1);
            s[nt][3] = exp2f(s[nt][3] - mn1);
            ls0 += s[nt][0] + s[nt][1];
            ls1 += s[nt][2] + s[nt][3];
        }
        ls0 += __shfl_xor_sync(0xffffffffu, ls0, 1);
        ls0 += __shfl_xor_sync(0xffffffffu, ls0, 2);
        ls1 += __shfl_xor_sync(0xffffffffu, ls1, 1);
        ls1 += __shfl_xor_sync(0xffffffffu, ls1, 2);
        l0 = l0 * sc0 + ls0;
        l1 = l1 * sc1 + ls1;

        #pragma unroll
        for (int nt = 0; nt < 8; nt++) {
            o[nt][0] *= sc0; o[nt][1] *= sc0;
            o[nt][2] *= sc1; o[nt][3] *= sc1;
        }

        // ---- write P (warp-private rows of dedicated P buffer) ----
        {
            int r0 = w * 16 + g;
            #pragma unroll
            for (int nt = 0; nt < 8; nt++) {
                int cc = nt * 8 + tig * 2;
                Pb[r0][cc]     = f2tf32(s[nt][0]);
                Pb[r0][cc + 1] = f2tf32(s[nt][1]);
                Pb[r0 + 8][cc]     = f2tf32(s[nt][2]);
                Pb[r0 + 8][cc + 1] = f2tf32(s[nt][3]);
            }
        }
        __syncwarp();

        // ---- O += P @ V ----
        #pragma unroll
        for (int ks = 0; ks < 8; ks++) {
            int r0 = w * 16 + g;
            unsigned ap0 = Pb[r0][ks * 8 + tig];
            unsigned ap1 = Pb[r0 + 8][ks * 8 + tig];
            unsigned ap2 = Pb[r0][ks * 8 + tig + 4];
            unsigned ap3 = Pb[r0 + 8][ks * 8 + tig + 4];
            #pragma unroll
            for (int nt = 0; nt < 8; nt++) {
                unsigned b0 = Vb[ks * 8 + tig][nt * 8 + g];
                unsigned b1 = Vb[ks * 8 + tig + 4][nt * 8 + g];
                mma_tf32(o[nt][0], o[nt][1], o[nt][2], o[nt][3],
                         ap0, ap1, ap2, ap3, b0, b1);
            }
        }
        __syncthreads();   // all warps done with K/V[buf] before it is refilled
    }

    float inv0 = 1.f / l0, inv1 = 1.f / l1;
    #pragma unroll
    for (int nt = 0; nt < 8; nt++) {
        int col = nt * 8 + tig * 2;
        float2 r0; r0.x = round_tf32(o[nt][0] * inv0); r0.y = round_tf32(o[nt][1] * inv0);
        float2 r1; r1.x = round_tf32(o[nt][2] * inv1); r1.y = round_tf32(o[nt][3] * inv1);
        *(float2*)(O + base + (size_t)qrow0 * D_MODEL + col) = r0;
        *(float2*)(O + base + (size_t)qrow1 * D_MODEL + col) = r1;
    }
}

// ---------------------------------------------------------------------------
// Launch
// ---------------------------------------------------------------------------
extern "C" void kernel_launch(void* const* d_in, const int* in_sizes, int n_in,
                              void* d_out, int out_size) {
    const float* x   = (const float*)d_in[0];
    const float* Wq  = (const float*)d_in[1];
    const float* bq  = (const float*)d_in[2];
    const float* Wk  = (const float*)d_in[3];
    const float* bk  = (const float*)d_in[4];
    const float* Wv  = (const float*)d_in[5];
    const float* bv  = (const float*)d_in[6];
    const float* Wo  = (const float*)d_in[7];
    const float* W1  = (const float*)d_in[8];
    const float* b1  = (const float*)d_in[9];
    const float* W2  = (const float*)d_in[10];
    const float* b2  = (const float*)d_in[11];
    const float* g1  = (const float*)d_in[12];
    const float* be1 = (const float*)d_in[13];
    const float* g2  = (const float*)d_in[14];
    const float* be2 = (const float*)d_in[15];
    float* out = (float*)d_out;

    float *ln, *q, *k, *v, *attn, *x1, *h;
    float *wq, *wk, *wv, *wo, *w1, *w2;
    cudaGetSymbolAddress((void**)&ln,   g_ln);
    cudaGetSymbolAddress((void**)&q,    g_q);
    cudaGetSymbolAddress((void**)&k,    g_k);
    cudaGetSymbolAddress((void**)&v,    g_v);
    cudaGetSymbolAddress((void**)&attn, g_attn);
    cudaGetSymbolAddress((void**)&x1,   g_x1);
    cudaGetSymbolAddress((void**)&h,    g_h);
    cudaGetSymbolAddress((void**)&wq,   g_wq);
    cudaGetSymbolAddress((void**)&wk,   g_wk);
    cudaGetSymbolAddress((void**)&wv,   g_wv);
    cudaGetSymbolAddress((void**)&wo,   g_wo);
    cudaGetSymbolAddress((void**)&w1,   g_w1);
    cudaGetSymbolAddress((void**)&w2,   g_w2);

    cudaFuncSetAttribute(flash_mma_kernel,
                         cudaFuncAttributeMaxDynamicSharedMemorySize, FLASH_SMEM);

    dim3 gemm_d(D_MODEL / BN, T_TOKENS / BM);        // (8, 64)
    dim3 gemm_qkv(D_MODEL / BN, T_TOKENS / BM, 3);   // (8, 64, 3)
    dim3 gemm_ff1(D_FF / BN, T_TOKENS / BM);         // (32, 64)

    // 0) round + transpose weights (Wt[n][k]); 4 DxD batched + W1 + W2
    dim3 tB(32, 8);
    dim3 tDD4(D_MODEL / 32, D_MODEL / 32, 4);
    dim3 tDF(D_FF / 32, D_MODEL / 32);
    dim3 tFD(D_MODEL / 32, D_FF / 32);
    round_transpose4_kernel<<<tDD4, tB>>>(Wq, Wk, Wv, Wo, wq, wk, wv, wo);
    round_transpose_kernel<<<tDF, tB>>>(W1, w1, D_MODEL, D_FF);
    round_transpose_kernel<<<tFD, tB>>>(W2, w2, D_FF, D_MODEL);

    // 1) ln1 = LN(x; g1, beta1)   [tf32-rounded output]
    layernorm_kernel<<<T_TOKENS, 256>>>(x, g1, be1, ln);
    // 2) Q,K,V = ln1 @ W* + b*   (fused launch; outputs tf32-rounded)
    gemm_qkv_kernel<<<gemm_qkv, 128>>>(ln, wq, bq, q, wk, bk, k, wv, bv, v);
    // 3) causal flash attention (FB_Q=64, cp.async double-buffered K/V)
    flash_mma_kernel<<<dim3(SEQ / FB_Q, BATCH * N_HEADS), 128, FLASH_SMEM>>>(q, k, v, attn);
    // 4) x1 = x + attn @ Wo      (no bias on o-proj; full fp32 residual)
    gemm_tf32_kernel<1><<<gemm_d, 128>>>(attn, wo, nullptr, x, x1, D_MODEL, D_MODEL);
    // 5) ln2 = LN(x1; g2, beta2) [tf32-rounded output]
    layernorm_kernel<<<T_TOKENS, 256>>>(x1, g2, be2, ln);
    // 6) h = gelu(ln2 @ W1 + b1) [tf32-rounded output]
    gemm_tf32_kernel<2><<<gemm_ff1, 128>>>(ln, w1, b1, nullptr, h, D_FF, D_MODEL);
    // 7) out = x1 + h @ W2 + b2  (full fp32 output)
    gemm_tf32_kernel<1><<<gemm_d, 128>>>(h, w2, b2, x1, out, D_MODEL, D_FF);
}